// round 9
// baseline (speedup 1.0000x reference)
#include <cuda_runtime.h>

// Problem constants (fixed by the dataset's setup_inputs)
#define BB 1024
#define TT 512
#define CC 64
#define TAG_START 62
#define TAG_STOP  63

typedef unsigned long long ull;

// Scratch (no device allocation allowed -> __device__ globals)
__device__ float gRes[BB];           // per-batch (logZ - gold)
__device__ unsigned int gTicket = 0; // self-resetting completion ticket (wraps mod BB)

// ---------------------------------------------------------------------------
// Packed f32x2 helpers (sm_100+)
// ---------------------------------------------------------------------------
__device__ __forceinline__ ull ffma2(ull a, ull b, ull c) {
    ull d;
    asm("fma.rn.f32x2 %0, %1, %2, %3;" : "=l"(d) : "l"(a), "l"(b), "l"(c));
    return d;
}
__device__ __forceinline__ ull fadd2(ull a, ull b) {
    ull d;
    asm("add.rn.f32x2 %0, %1, %2;" : "=l"(d) : "l"(a), "l"(b));
    return d;
}
__device__ __forceinline__ float2 upk2(ull a) {
    float2 f;
    asm("mov.b64 {%0, %1}, %2;" : "=f"(f.x), "=f"(f.y) : "l"(a));
    return f;
}
__device__ __forceinline__ ull pk2(float x, float y) {
    ull d;
    asm("mov.b64 %0, {%1, %2};" : "=l"(d) : "f"(x), "f"(y));
    return d;
}
__device__ __forceinline__ unsigned smem_u32(const void* p_) {
    unsigned a;
    asm("{ .reg .u64 t; cvta.to.shared.u64 t, %1; cvt.u32.u64 %0, t; }"
        : "=r"(a) : "l"(p_));
    return a;
}
__device__ __forceinline__ void cp_async16(unsigned s, const void* g) {
    asm volatile("cp.async.ca.shared.global [%0], [%1], 16;" :: "r"(s), "l"(g));
}
__device__ __forceinline__ void cp_commit() {
    asm volatile("cp.async.commit_group;");
}
template <int N>
__device__ __forceinline__ void cp_wait() {
    asm volatile("cp.async.wait_group %0;" :: "n"(N));
}

// ---------------------------------------------------------------------------
// Fused CRF kernel: ONE WARP (32 threads) per batch element (R7 shape — the
// 2-warp split regressed: per-step cross-SMSP __syncthreads + STS drains cost
// more than the spills it removed). Thread l owns tag columns j0=2l, j0+1.
// Spill fix vs R7: the 16-deep float2 emission register buffer (32 regs +
// 8 LDG address temps) is replaced by cp.async GMEM->SMEM staging, 8-step
// groups, double buffered. Register demand ~165 < 255 -> no local spills.
//   state: p[j] = exp(alpha[j] - M) in shared, M = running log-scale.
//   step:  q[j] = sum_i p[i]*E[i][j]  (packed f32x2 over i, 64 ffma2/thread),
//          p_new[j] = q[j] * exp(emit[t][j])
//   renorm every 8 steps (8*10.3 < 88.7 fp32 overflow margin).
// Gold path fused. Tags arrive int32 (JAX x64-off coercion).
// Last finishing block (atomicInc ticket) does the deterministic mean.
// ---------------------------------------------------------------------------
__global__ __launch_bounds__(32) void crf_fused_kernel(
    const float* __restrict__ emissions,      // (B, T, C) f32
    const float* __restrict__ trans,          // (C, C)    f32
    const int* __restrict__ tags,             // (B, T)    i32
    const int* __restrict__ mask,             // (B, T)    i32
    float* __restrict__ out)                  // scalar
{
    __shared__ __align__(16) float p[2][CC];
    __shared__ __align__(16) float stage[2][8][CC];   // emission staging, 2x2KB
    __shared__ unsigned char tagS[TT];
    __shared__ unsigned char maskS[TT];

    const int l = threadIdx.x;   // 0..31
    const int b = blockIdx.x;
    const int j0 = 2 * l;

    const float* eb = emissions + (size_t)b * TT * CC;

    // Stage tags/mask for this sequence into shared (u8)
    for (int k = l; k < TT; k += 32) {
        tagS[k]  = (unsigned char)tags[(size_t)b * TT + k];
        maskS[k] = (unsigned char)(mask[(size_t)b * TT + k] != 0);
    }

    // E columns for j0,j0+1 packed across i: EA[m]=(E[2m][j0],E[2m+1][j0]).
    // expf(-10000) underflows to 0 == forbidden transition. trans is L2-hot.
    ull EA[CC / 2], EB[CC / 2];
#pragma unroll
    for (int m = 0; m < CC / 2; m++) {
        float2 v0 = *(const float2*)(trans + (size_t)(2 * m) * CC + j0);
        float2 v1 = *(const float2*)(trans + (size_t)(2 * m + 1) * CC + j0);
        EA[m] = pk2(expf(v0.x), expf(v1.x));
        EB[m] = pk2(expf(v0.y), expf(v1.y));
    }

    // init p
    float cur0 = (j0 == TAG_START) ? 1.0f : 0.0f;
    float cur1 = (j0 + 1 == TAG_START) ? 1.0f : 0.0f;
    *(float2*)&p[0][j0] = make_float2(cur0, cur1);

    float M = 0.0f;          // log-scale (identical in all lanes)
    float gold = 0.0f;       // this lane's gold-score contributions
    int prev = TAG_START;    // previous tag (identical in all lanes)

    // cp.async prefetch of one 8-step group: 2KB contiguous, 4x16B per lane.
    const unsigned stA = smem_u32(&stage[0][0][0]);
#define PREFETCH(G)                                                          \
    {                                                                        \
        const float* gsrc = eb + (size_t)(G) * 8 * CC;                       \
        unsigned sdst = stA + (((G) & 1) ? 2048u : 0u);                      \
        _Pragma("unroll")                                                    \
        for (int c = 0; c < 4; c++)                                          \
            cp_async16(sdst + (unsigned)(c * 512 + l * 16),                  \
                       gsrc + c * 128 + l * 4);                              \
        cp_commit();                                                         \
    }

    PREFETCH(0)

    for (int g = 0; g < TT / 8; g++) {
        if (g + 1 < TT / 8) { PREFETCH(g + 1) cp_wait<1>(); }
        else                { cp_wait<0>(); }
        __syncthreads();    // 1-warp CTA: BAR floor ~3cyc; cross-lane cp.async vis

        const float* es = &stage[g & 1][0][0];
#pragma unroll
        for (int s = 0; s < 8; s++) {
            const int t = g * 8 + s;
            const int tg = tagS[t];
            const int m  = maskS[t];

            // q[j] = sum_i p[i]*E[i][j] -- 16 LDS.128 + 64 ffma2
            const ulonglong2* pv = (const ulonglong2*)&p[s & 1][0];
            ull a0 = 0ull, a1 = 0ull, b0 = 0ull, b1 = 0ull;
#pragma unroll
            for (int k = 0; k < CC / 4; k++) {
                ulonglong2 v = pv[k];
                a0 = ffma2(EA[2 * k],     v.x, a0);
                a1 = ffma2(EA[2 * k + 1], v.y, a1);
                b0 = ffma2(EB[2 * k],     v.x, b0);
                b1 = ffma2(EB[2 * k + 1], v.y, b1);
            }
            float2 qa = upk2(fadd2(a0, a1));
            float2 qb = upk2(fadd2(b0, b1));
            float qA = qa.x + qa.y;
            float qB = qb.x + qb.y;

            float2 e = *(const float2*)(es + s * CC + j0);   // conflict-free LDS.64
            float pn0 = m ? (qA * __expf(e.x)) : cur0;
            float pn1 = m ? (qB * __expf(e.y)) : cur1;

            if (m && (tg >> 1) == l)
                gold += ((tg & 1) ? e.y : e.x) + trans[prev * CC + tg];
            if (m) prev = tg;

            if (s == 7) {   // renorm every 8 steps (pure warp-shuffle)
                float sm = pn0 + pn1;
#pragma unroll
                for (int o = 16; o > 0; o >>= 1)
                    sm += __shfl_xor_sync(0xffffffffu, sm, o);
                M += __logf(sm);
                float r = 1.0f / sm;
                pn0 *= r; pn1 *= r;
            }

            *(float2*)&p[(s + 1) & 1][j0] = make_float2(pn0, pn1);
            __syncwarp();
            cur0 = pn0; cur1 = pn1;
        }
    }
#undef PREFETCH

    // log_Z = M + log( sum_j p[j] * exp(trans[j][STOP]) )
    // (cur0/cur1 hold final p; t=511 hit the renorm so they are normalized)
    float v = cur0 * __expf(trans[j0 * CC + TAG_STOP])
            + cur1 * __expf(trans[(j0 + 1) * CC + TAG_STOP]);
#pragma unroll
    for (int o = 16; o > 0; o >>= 1)
        v += __shfl_xor_sync(0xffffffffu, v, o);
    float logZ = M + __logf(v);

#pragma unroll
    for (int o = 16; o > 0; o >>= 1)
        gold += __shfl_xor_sync(0xffffffffu, gold, o);

    if (l == 0) {
        float g = gold + trans[prev * CC + TAG_STOP];
        gRes[b] = logZ - g;
    }
    __threadfence();

    // Last block to finish computes the deterministic mean.
    unsigned int old = 0;
    if (l == 0) old = atomicInc(&gTicket, BB - 1);   // wraps to 0 after BB
    old = __shfl_sync(0xffffffffu, old, 0);
    if (old == BB - 1) {
        __threadfence();
        float a = 0.0f;
        for (int k = l; k < BB; k += 32)
            a += *((volatile float*)&gRes[k]);       // fixed order -> deterministic
#pragma unroll
        for (int o = 16; o > 0; o >>= 1)
            a += __shfl_xor_sync(0xffffffffu, a, o);
        if (l == 0) out[0] = a * (1.0f / BB);
    }
}

// ---------------------------------------------------------------------------
extern "C" void kernel_launch(void* const* d_in, const int* in_sizes, int n_in,
                              void* d_out, int out_size) {
    const float* emissions = (const float*)d_in[0];
    const float* trans     = (const float*)d_in[1];
    const int*   tags      = (const int*)d_in[2];   // int32 (JAX x64 off)
    const int*   mask      = (const int*)d_in[3];
    float* out = (float*)d_out;

    crf_fused_kernel<<<BB, 32>>>(emissions, trans, tags, mask, out);
}